// round 7
// baseline (speedup 1.0000x reference)
#include <cuda_runtime.h>
#include <math.h>

#define MAXN   16384
#define HDIM   128
#define TM     128
#define NSTEPS 64
#define THRS   5e-5f

// ---------------- device state ----------------
__device__ float g_start[MAXN], g_end[MAXN];
__device__ float g_next_s[MAXN], g_next_e[MAXN];
__device__ float g_curr_s[MAXN], g_curr_e[MAXN];
__device__ unsigned char g_uf_s[MAXN], g_uf_e[MAXN];
__device__ unsigned char g_nps[MAXN], g_npe[MAXN];
__device__ unsigned char g_workf[MAXN], g_secf[MAXN], g_convf[MAXN];
__device__ float g_sdfval[MAXN * NSTEPS];
__device__ float g_zlow[MAXN], g_zhigh[MAXN], g_slow[MAXN], g_shigh[MAXN];
__device__ float g_zpred[MAXN], g_cand[MAXN], g_smv[MAXN];

// jax.nn.softplus(x) = logaddexp(x,0) = max(x,0) + log1p(exp(-|x|))
__device__ __forceinline__ float softplus_x(float x) {
    return __fadd_rn(fmaxf(x, 0.0f), log1pf(expf(-fabsf(x))));
}

// jnp.linspace(0,1,64)[i]
__device__ __forceinline__ float lint(int i) {
    return (i == 63) ? 1.0f : __fdiv_rn((float)i, 63.0f);
}

// pts_int = start + t*(end-start), uncontracted rn ops
__device__ __forceinline__ float ptsint(float s, float e, float t) {
    return __fadd_rn(s, __fmul_rn(t, __fsub_rn(e, s)));
}

// ---------------- shared layout (floats) ----------------
#define SOFF_W2   0
#define SOFF_HST  16384
#define SOFF_H3   32768
#define SOFF_PS   49280
#define SOFF_W1   49792
#define SOFF_B1   50176
#define SOFF_B2   50304
#define SOFF_W3   50432
#define SOFF_B3   50560
#define SOFF_OIX  50564
#define EVAL_SMEM ((50564 + 132) * 4)

// Dense predicated MLP-SDF eval, fp32, XLA/cuBLAS-matched orderings.
__global__ void __launch_bounds__(256, 1) eval_kernel(
    int mode, int wz, int npts,
    const float* __restrict__ rayo, const float* __restrict__ rayd,
    const float* __restrict__ W1, const float* __restrict__ b1,
    const float* __restrict__ W2, const float* __restrict__ b2,
    const float* __restrict__ W3, const float* __restrict__ b3,
    const unsigned char* __restrict__ pred, const float* __restrict__ tvals,
    float* __restrict__ outp)
{
    extern __shared__ float sbuf[];
    float* W2s = sbuf + SOFF_W2;
    float* HsT = sbuf + SOFF_HST;
    float* H3  = sbuf + SOFF_H3;
    float* Ps  = sbuf + SOFF_PS;
    float* w1s = sbuf + SOFF_W1;
    float* b1s = sbuf + SOFF_B1;
    float* b2s = sbuf + SOFF_B2;
    float* w3s = sbuf + SOFF_W3;
    float* b3s = sbuf + SOFF_B3;
    int*   oix = (int*)(sbuf + SOFF_OIX);

    const int tid = threadIdx.x;

    for (int i = tid; i < HDIM * HDIM; i += 256) W2s[i] = W2[i];
    for (int i = tid; i < 3 * HDIM; i += 256)    w1s[i] = W1[i];
    if (tid < HDIM) { b1s[tid] = b1[tid]; b2s[tid] = b2[tid]; w3s[tid] = W3[tid]; }
    if (tid == 0) b3s[0] = b3[0];

    if (tid < TM) {
        int li = blockIdx.x * TM + tid;
        int code = 0;          // 0: no write; +k: write sdf to k-1; -k: write 0 to k-1
        float px = 0.f, py = 0.f, pz = 0.f;
        if (li < npts) {
            int ray = (mode == 0) ? li : (li >> 6);
            bool pr = (pred[ray] != 0);
            if (pr) {
                float t;
                if (mode == 0) t = tvals[ray];
                else           t = ptsint(g_start[ray], g_end[ray], lint(li & 63));
                px = __fadd_rn(rayo[ray * 3 + 0], __fmul_rn(t, rayd[ray * 3 + 0]));
                py = __fadd_rn(rayo[ray * 3 + 1], __fmul_rn(t, rayd[ray * 3 + 1]));
                pz = __fadd_rn(rayo[ray * 3 + 2], __fmul_rn(t, rayd[ray * 3 + 2]));
                code = li + 1;
            } else if (wz) {
                code = -(li + 1);
            }
        }
        Ps[tid * 4 + 0] = px; Ps[tid * 4 + 1] = py; Ps[tid * 4 + 2] = pz; Ps[tid * 4 + 3] = 0.f;
        oix[tid] = code;
    }
    __syncthreads();

    // layer 1: ascending-k fma chain from 0, bias after (cuBLAS + XLA order)
    for (int idx = tid; idx < HDIM * TM; idx += 256) {
        int k = idx >> 7, m = idx & 127;
        float v = __fmaf_rn(Ps[m * 4 + 0], w1s[k], 0.0f);
        v = __fmaf_rn(Ps[m * 4 + 1], w1s[HDIM + k], v);
        v = __fmaf_rn(Ps[m * 4 + 2], w1s[2 * HDIM + k], v);
        v = __fadd_rn(v, b1s[k]);
        HsT[k * TM + m] = softplus_x(v);
    }
    __syncthreads();

    // layer 2: acc=0, ascending-k fma per element; bias after (cuBLAS tile order)
    const int tx = tid & 15, ty = tid >> 4;
    float acc[8][8];
    #pragma unroll
    for (int i = 0; i < 8; i++)
        #pragma unroll
        for (int j = 0; j < 8; j++) acc[i][j] = 0.0f;
    const float* hp = HsT + ty * 8;
    const float* wp = W2s + tx * 8;
    #pragma unroll 4
    for (int k = 0; k < HDIM; k++) {
        float4 a0 = *(const float4*)(hp + k * TM);
        float4 a1 = *(const float4*)(hp + k * TM + 4);
        float4 c0 = *(const float4*)(wp + k * HDIM);
        float4 c1 = *(const float4*)(wp + k * HDIM + 4);
        float av[8] = {a0.x, a0.y, a0.z, a0.w, a1.x, a1.y, a1.z, a1.w};
        float bv[8] = {c0.x, c0.y, c0.z, c0.w, c1.x, c1.y, c1.z, c1.w};
        #pragma unroll
        for (int i = 0; i < 8; i++)
            #pragma unroll
            for (int j = 0; j < 8; j++)
                acc[i][j] = __fmaf_rn(av[i], bv[j], acc[i][j]);
    }
    #pragma unroll
    for (int i = 0; i < 8; i++) {
        int m = ty * 8 + i;
        #pragma unroll
        for (int j = 0; j < 8; j++) {
            int n = tx * 8 + j;
            float h2 = __fadd_rn(acc[i][j], b2s[n]);
            H3[m * 129 + n] = softplus_x(h2);
        }
    }
    __syncthreads();

    // layer 3: cuBLAS gemv2T order — 8 threads per output, stride-8 ascending
    // fma chains of 16, then 3-level shuffle tree over the 8 partials; + b3 after.
    {
        int grp = tid >> 3;       // 0..31: 8-lane group id
        int l8  = tid & 7;        // lane within group
        #pragma unroll
        for (int rep = 0; rep < 4; rep++) {
            int m = rep * 32 + grp;
            const float* hrow = H3 + m * 129;
            float p = 0.0f;
            #pragma unroll
            for (int i = 0; i < 16; i++)
                p = __fmaf_rn(hrow[l8 + 8 * i], w3s[l8 + 8 * i], p);
            p = __fadd_rn(p, __shfl_down_sync(0xffffffffu, p, 4, 8));
            p = __fadd_rn(p, __shfl_down_sync(0xffffffffu, p, 2, 8));
            p = __fadd_rn(p, __shfl_down_sync(0xffffffffu, p, 1, 8));
            if (l8 == 0) {
                float corr = __fadd_rn(p, b3s[0]);
                float px = Ps[m * 4 + 0], py = Ps[m * 4 + 1], pz = Ps[m * 4 + 2];
                float s2 = __fadd_rn(__fadd_rn(__fmul_rn(px, px), __fmul_rn(py, py)), __fmul_rn(pz, pz));
                float nr = __fsqrt_rn(s2);
                float sv = __fadd_rn(__fsub_rn(nr, 1.0f), __fmul_rn(0.1f, corr));
                int code = oix[m];
                if (code > 0)      outp[code - 1] = sv;
                else if (code < 0) outp[-code - 1] = 0.0f;
            }
        }
    }
}

// ---------------- control kernels (dense, no atomics) ----------------
__global__ void init_kernel(const float* __restrict__ fb, const int* __restrict__ mi, int N) {
    int i = blockIdx.x * blockDim.x + threadIdx.x;
    if (i >= N) return;
    g_start[i] = fb[2 * i];
    g_end[i]   = fb[2 * i + 1];
    unsigned char m = mi[i] ? 1 : 0;
    g_uf_s[i] = m; g_uf_e[i] = m;
    g_next_s[i] = 0.f; g_next_e[i] = 0.f;
    g_workf[i] = 0; g_secf[i] = 0; g_convf[i] = 0;
    g_nps[i] = 0; g_npe[i] = 0;
}

__global__ void update1_kernel(int apply_lt, int N) {
    int i = blockIdx.x * blockDim.x + threadIdx.x;
    if (i >= N) return;
    unsigned char us = g_uf_s[i], ue = g_uf_e[i];
    float s = g_start[i], e = g_end[i];
    if (apply_lt) { unsigned char lt = (s < e) ? 1 : 0; us &= lt; ue &= lt; }
    float cs = us ? g_next_s[i] : 0.f; if (cs <= THRS) cs = 0.f;
    float ce = ue ? g_next_e[i] : 0.f; if (ce <= THRS) ce = 0.f;
    us = (us && cs > THRS) ? 1 : 0;
    ue = (ue && ce > THRS) ? 1 : 0;
    if (us) s = __fadd_rn(s, cs);
    if (ue) e = __fsub_rn(e, ce);
    g_start[i] = s; g_end[i] = e;
    g_curr_s[i] = cs; g_curr_e[i] = ce;
    g_uf_s[i] = us; g_uf_e[i] = ue;
}

__global__ void linestep_kernel(int N) {
    int i = blockIdx.x * blockDim.x + threadIdx.x;
    if (i >= N) return;
    unsigned char ns = 0, ne = 0;
    if (g_uf_s[i] && g_next_s[i] < 0.f) {
        g_start[i] = __fsub_rn(g_start[i], __fmul_rn(0.5f, g_curr_s[i]));
        ns = 1;
    }
    if (g_uf_e[i] && g_next_e[i] < 0.f) {
        g_end[i] = __fadd_rn(g_end[i], __fmul_rn(0.5f, g_curr_e[i]));
        ne = 1;
    }
    g_nps[i] = ns; g_npe[i] = ne;
}

__global__ void work_kernel(int N) {
    int i = blockIdx.x * blockDim.x + threadIdx.x;
    if (i >= N) return;
    unsigned char us = g_uf_s[i];
    if (!(g_start[i] < g_end[i])) us = 0;
    g_workf[i] = (us && (g_next_s[i] > THRS)) ? 1 : 0;
}

// one warp per ray: argmins over the 64 dense samples + secant init
__global__ void reduce_kernel(const int* __restrict__ obj, int N) {
    int warp = threadIdx.x >> 5, lane = threadIdx.x & 31;
    int ray = blockIdx.x * 8 + warp;
    if (ray >= N || !g_workf[ray]) return;
    float s0 = g_sdfval[ray * 64 + lane];
    float s1 = g_sdfval[ray * 64 + lane + 32];
    float sg0 = (s0 > 0.f ? 1.f : (s0 < 0.f ? -1.f : 0.f));
    float sg1 = (s1 > 0.f ? 1.f : (s1 < 0.f ? -1.f : 0.f));
    float t0 = sg0 * (float)(64 - lane);
    float t1 = sg1 * (float)(32 - lane);

    float bv; int bi;
    if (t1 < t0) { bv = t1; bi = lane + 32; } else { bv = t0; bi = lane; }
    float cv; int ci;
    if (s1 < s0) { cv = s1; ci = lane + 32; } else { cv = s0; ci = lane; }
    #pragma unroll
    for (int off = 16; off > 0; off >>= 1) {
        float ov = __shfl_down_sync(0xffffffffu, bv, off);
        int   oi = __shfl_down_sync(0xffffffffu, bi, off);
        if (ov < bv || (ov == bv && oi < bi)) { bv = ov; bi = oi; }
        float pv = __shfl_down_sync(0xffffffffu, cv, off);
        int   pi = __shfl_down_sync(0xffffffffu, ci, off);
        if (pv < cv || (pv == cv && pi < ci)) { cv = pv; ci = pi; }
    }
    if (lane == 0) {
        int idx = bi;
        bool net = (bv < 0.f);
        int out_idx = ci;
        bool ob = (obj[ray] != 0);
        bool p_out = !(ob && net);
        int sel = p_out ? out_idx : idx;
        float s = g_start[ray], e = g_end[ray];
        g_cand[ray]  = ptsint(s, e, lint(sel));
        g_convf[ray] = net ? 1 : 0;
        if (net && ob) {
            g_secf[ray] = 1;
            int il = (idx + 63) & 63;
            float zh = ptsint(s, e, lint(idx));
            float zl = ptsint(s, e, lint(il));
            float sh = g_sdfval[ray * 64 + idx];
            float sl = g_sdfval[ray * 64 + il];
            g_zlow[ray] = zl; g_zhigh[ray] = zh; g_slow[ray] = sl; g_shigh[ray] = sh;
            float num = __fmul_rn(-sl, __fsub_rn(zh, zl));
            float den = __fadd_rn(__fsub_rn(sh, sl), 1e-10f);
            g_zpred[ray] = __fadd_rn(__fdiv_rn(num, den), zl);
        }
    }
}

__global__ void secant_kernel(int N) {
    int i = blockIdx.x * blockDim.x + threadIdx.x;
    if (i >= N || !g_secf[i]) return;
    float smv = g_smv[i];
    float zl = g_zlow[i], zh = g_zhigh[i], sl = g_slow[i], sh = g_shigh[i];
    float zp = g_zpred[i];
    if (smv > 0.f) { zl = zp; sl = smv; }
    if (smv < 0.f) { zh = zp; sh = smv; }
    float num = __fmul_rn(-sl, __fsub_rn(zh, zl));
    float den = __fadd_rn(__fsub_rn(sh, sl), 1e-10f);
    zp = __fadd_rn(__fdiv_rn(num, den), zl);
    g_zlow[i] = zl; g_zhigh[i] = zh; g_slow[i] = sl; g_shigh[i] = sh;
    g_zpred[i] = zp;
}

__global__ void assembly_kernel(const float* __restrict__ rayo, const float* __restrict__ rayd,
                                float* __restrict__ out, int N) {
    int i = blockIdx.x * blockDim.x + threadIdx.x;
    if (i >= N) return;
    float px = 0.f, py = 0.f, pz = 0.f, dist = 0.f;
    if (g_secf[i]) {
        float t = g_zpred[i];
        px = __fadd_rn(rayo[i*3+0], __fmul_rn(t, rayd[i*3+0]));
        py = __fadd_rn(rayo[i*3+1], __fmul_rn(t, rayd[i*3+1]));
        pz = __fadd_rn(rayo[i*3+2], __fmul_rn(t, rayd[i*3+2]));
        dist = t;
    } else if (g_workf[i]) {
        float t = g_cand[i];
        px = __fadd_rn(rayo[i*3+0], __fmul_rn(t, rayd[i*3+0]));
        py = __fadd_rn(rayo[i*3+1], __fmul_rn(t, rayd[i*3+1]));
        pz = __fadd_rn(rayo[i*3+2], __fmul_rn(t, rayd[i*3+2]));
        dist = t;
    }
    out[i*5+0] = px; out[i*5+1] = py; out[i*5+2] = pz;
    out[i*5+3] = dist;
    out[i*5+4] = g_convf[i] ? 1.0f : 0.0f;
}

// ---------------- host orchestration ----------------
extern "C" void kernel_launch(void* const* d_in, const int* in_sizes, int n_in,
                              void* d_out, int out_size)
{
    const float* rayo = (const float*)d_in[0];
    const float* rayd = (const float*)d_in[1];
    const float* fb   = (const float*)d_in[2];
    const float* W1   = (const float*)d_in[3];
    const float* b1   = (const float*)d_in[4];
    const float* W2   = (const float*)d_in[5];
    const float* b2   = (const float*)d_in[6];
    const float* W3   = (const float*)d_in[7];
    const float* b3   = (const float*)d_in[8];
    const int* obj    = (const int*)d_in[9];
    const int* mi     = (const int*)d_in[10];
    int N = in_sizes[0] / 3;
    float* out = (float*)d_out;

    cudaFuncSetAttribute(eval_kernel, cudaFuncAttributeMaxDynamicSharedMemorySize, EVAL_SMEM);

    float *p_start, *p_end, *p_ns, *p_ne, *p_zpred, *p_smv, *p_sdfval;
    unsigned char *p_ufs, *p_ufe, *p_nps, *p_npe, *p_workf, *p_secf;
    cudaGetSymbolAddress((void**)&p_start,  g_start);
    cudaGetSymbolAddress((void**)&p_end,    g_end);
    cudaGetSymbolAddress((void**)&p_ns,     g_next_s);
    cudaGetSymbolAddress((void**)&p_ne,     g_next_e);
    cudaGetSymbolAddress((void**)&p_zpred,  g_zpred);
    cudaGetSymbolAddress((void**)&p_smv,    g_smv);
    cudaGetSymbolAddress((void**)&p_sdfval, g_sdfval);
    cudaGetSymbolAddress((void**)&p_ufs,    g_uf_s);
    cudaGetSymbolAddress((void**)&p_ufe,    g_uf_e);
    cudaGetSymbolAddress((void**)&p_nps,    g_nps);
    cudaGetSymbolAddress((void**)&p_npe,    g_npe);
    cudaGetSymbolAddress((void**)&p_workf,  g_workf);
    cudaGetSymbolAddress((void**)&p_secf,   g_secf);

    const int nb  = (N + 255) / 256;
    const int eg  = (N + TM - 1) / TM;          // 128 blocks
    const int egd = (N * NSTEPS + TM - 1) / TM; // 8192 blocks

    init_kernel<<<nb, 256>>>(fb, mi, N);
    eval_kernel<<<eg, 256, EVAL_SMEM>>>(0, 1, N, rayo, rayd, W1, b1, W2, b2, W3, b3, p_ufs, p_start, p_ns);
    eval_kernel<<<eg, 256, EVAL_SMEM>>>(0, 1, N, rayo, rayd, W1, b1, W2, b2, W3, b3, p_ufe, p_end,   p_ne);

    for (int it = 0; it < 10; it++) {
        update1_kernel<<<nb, 256>>>(it > 0 ? 1 : 0, N);
        eval_kernel<<<eg, 256, EVAL_SMEM>>>(0, 1, N, rayo, rayd, W1, b1, W2, b2, W3, b3, p_ufs, p_start, p_ns);
        eval_kernel<<<eg, 256, EVAL_SMEM>>>(0, 1, N, rayo, rayd, W1, b1, W2, b2, W3, b3, p_ufe, p_end,   p_ne);
        linestep_kernel<<<nb, 256>>>(N);
        eval_kernel<<<eg, 256, EVAL_SMEM>>>(0, 0, N, rayo, rayd, W1, b1, W2, b2, W3, b3, p_nps, p_start, p_ns);
        eval_kernel<<<eg, 256, EVAL_SMEM>>>(0, 0, N, rayo, rayd, W1, b1, W2, b2, W3, b3, p_npe, p_end,   p_ne);
    }

    work_kernel<<<nb, 256>>>(N);
    eval_kernel<<<egd, 256, EVAL_SMEM>>>(1, 0, N * NSTEPS, rayo, rayd, W1, b1, W2, b2, W3, b3, p_workf, p_start, p_sdfval);
    reduce_kernel<<<(N + 7) / 8, 256>>>(obj, N);

    for (int it = 0; it < 8; it++) {
        eval_kernel<<<eg, 256, EVAL_SMEM>>>(0, 0, N, rayo, rayd, W1, b1, W2, b2, W3, b3, p_secf, p_zpred, p_smv);
        secant_kernel<<<nb, 256>>>(N);
    }

    assembly_kernel<<<nb, 256>>>(rayo, rayd, out, N);
    (void)n_in; (void)out_size; (void)b2;
}

// round 8
// speedup vs baseline: 2.3841x; 2.3841x over previous
#include <cuda_runtime.h>
#include <math.h>

#define MAXN   16384
#define HDIM   128
#define TM     128
#define NSTEPS 64
#define THRS   5e-5f

// ---------------- device state ----------------
__device__ float g_start[MAXN], g_end[MAXN];
__device__ float g_next_s[MAXN], g_next_e[MAXN];
__device__ float g_curr_s[MAXN], g_curr_e[MAXN];
__device__ unsigned char g_uf_s[MAXN], g_uf_e[MAXN];
__device__ unsigned char g_workf[MAXN], g_secf[MAXN], g_convf[MAXN];
__device__ float g_sdfval[MAXN * NSTEPS];
__device__ float g_zlow[MAXN], g_zhigh[MAXN], g_slow[MAXN], g_shigh[MAXN];
__device__ float g_zpred[MAXN], g_cand[MAXN], g_smv[MAXN];
__device__ int g_cnt[64];
__device__ int g_la[MAXN], g_lb[MAXN], g_lc[MAXN], g_ld[MAXN], g_lw[MAXN], g_ls[MAXN];

// jax.nn.softplus(x) = max(x,0) + log1p(exp(-|x|))  [libdevice expf/log1pf]
__device__ __forceinline__ float softplus_x(float x) {
    return __fadd_rn(fmaxf(x, 0.0f), log1pf(expf(-fabsf(x))));
}
// jnp.linspace(0,1,64)[i]
__device__ __forceinline__ float lint(int i) {
    return (i == 63) ? 1.0f : __fdiv_rn((float)i, 63.0f);
}
// pts_int = start + t*(end-start), uncontracted rn
__device__ __forceinline__ float ptsint(float s, float e, float t) {
    return __fadd_rn(s, __fmul_rn(t, __fsub_rn(e, s)));
}

// ---------------- shared layout (floats) ----------------
#define SOFF_W2   0
#define SOFF_HST  16384
#define SOFF_H3   32768
#define SOFF_PS   49280
#define SOFF_W1   49792
#define SOFF_B1   50176
#define SOFF_B2   50304
#define SOFF_W3   50432
#define SOFF_B3   50560
#define SOFF_OIX  50564
#define EVAL_SMEM ((50564 + 132) * 4)

// Compacted predicated MLP-SDF eval; per-point math bit-identical to the
// passing r7 kernel (ascending-k fma, bias-after, gemv2T-8 layer 3).
// Side A: blocks [0, gridA); side B: blocks [gridA, grid).
// mode 0: li -> ray=list[li], t=tvals[ray], out[ray]
// mode 1: li -> ray=list[li>>6], step=li&63, t=ptsint(start,end,lint(step)), out[ray*64+step]
__global__ void __launch_bounds__(256, 1) eval_kernel(
    int mode, int cidxA, int cidxB, int gridA,
    const float* __restrict__ rayo, const float* __restrict__ rayd,
    const float* __restrict__ W1, const float* __restrict__ b1,
    const float* __restrict__ W2, const float* __restrict__ b2,
    const float* __restrict__ W3, const float* __restrict__ b3,
    const int* __restrict__ listA, const int* __restrict__ listB,
    const float* __restrict__ tvalsA, const float* __restrict__ tvalsB,
    float* __restrict__ outA, float* __restrict__ outB)
{
    extern __shared__ float sbuf[];
    float* W2s = sbuf + SOFF_W2;
    float* HsT = sbuf + SOFF_HST;
    float* H3  = sbuf + SOFF_H3;
    float* Ps  = sbuf + SOFF_PS;
    float* w1s = sbuf + SOFF_W1;
    float* b1s = sbuf + SOFF_B1;
    float* b2s = sbuf + SOFF_B2;
    float* w3s = sbuf + SOFF_W3;
    float* b3s = sbuf + SOFF_B3;
    int*   oix = (int*)(sbuf + SOFF_OIX);

    const int tid = threadIdx.x;
    const int side = (blockIdx.x >= gridA) ? 1 : 0;
    const int lb   = side ? (blockIdx.x - gridA) : blockIdx.x;
    int pcnt = g_cnt[side ? cidxB : cidxA];
    if (mode == 1) pcnt <<= 6;
    if (lb * TM >= pcnt) return;   // idle block

    const int*   list  = side ? listB  : listA;
    const float* tvals = side ? tvalsB : tvalsA;
    float*       outp  = side ? outB   : outA;

    for (int i = tid; i < HDIM * HDIM; i += 256) W2s[i] = W2[i];
    for (int i = tid; i < 3 * HDIM; i += 256)    w1s[i] = W1[i];
    if (tid < HDIM) { b1s[tid] = b1[tid]; b2s[tid] = b2[tid]; w3s[tid] = W3[tid]; }
    if (tid == 0) b3s[0] = b3[0];

    if (tid < TM) {
        int li = lb * TM + tid;
        int oi = -1;
        float px = 0.f, py = 0.f, pz = 0.f;
        if (li < pcnt) {
            int ray; float t;
            if (mode == 0) {
                ray = list[li];
                t = tvals[ray];
                oi = ray;
            } else {
                ray = list[li >> 6];
                t = ptsint(g_start[ray], g_end[ray], lint(li & 63));
                oi = ray * NSTEPS + (li & 63);
            }
            px = __fadd_rn(rayo[ray * 3 + 0], __fmul_rn(t, rayd[ray * 3 + 0]));
            py = __fadd_rn(rayo[ray * 3 + 1], __fmul_rn(t, rayd[ray * 3 + 1]));
            pz = __fadd_rn(rayo[ray * 3 + 2], __fmul_rn(t, rayd[ray * 3 + 2]));
        }
        Ps[tid * 4 + 0] = px; Ps[tid * 4 + 1] = py; Ps[tid * 4 + 2] = pz; Ps[tid * 4 + 3] = 0.f;
        oix[tid] = oi;
    }
    __syncthreads();

    // layer 1
    for (int idx = tid; idx < HDIM * TM; idx += 256) {
        int k = idx >> 7, m = idx & 127;
        float v = __fmaf_rn(Ps[m * 4 + 0], w1s[k], 0.0f);
        v = __fmaf_rn(Ps[m * 4 + 1], w1s[HDIM + k], v);
        v = __fmaf_rn(Ps[m * 4 + 2], w1s[2 * HDIM + k], v);
        v = __fadd_rn(v, b1s[k]);
        HsT[k * TM + m] = softplus_x(v);
    }
    __syncthreads();

    // layer 2
    const int tx = tid & 15, ty = tid >> 4;
    float acc[8][8];
    #pragma unroll
    for (int i = 0; i < 8; i++)
        #pragma unroll
        for (int j = 0; j < 8; j++) acc[i][j] = 0.0f;
    const float* hp = HsT + ty * 8;
    const float* wp = W2s + tx * 8;
    #pragma unroll 4
    for (int k = 0; k < HDIM; k++) {
        float4 a0 = *(const float4*)(hp + k * TM);
        float4 a1 = *(const float4*)(hp + k * TM + 4);
        float4 c0 = *(const float4*)(wp + k * HDIM);
        float4 c1 = *(const float4*)(wp + k * HDIM + 4);
        float av[8] = {a0.x, a0.y, a0.z, a0.w, a1.x, a1.y, a1.z, a1.w};
        float bv[8] = {c0.x, c0.y, c0.z, c0.w, c1.x, c1.y, c1.z, c1.w};
        #pragma unroll
        for (int i = 0; i < 8; i++)
            #pragma unroll
            for (int j = 0; j < 8; j++)
                acc[i][j] = __fmaf_rn(av[i], bv[j], acc[i][j]);
    }
    #pragma unroll
    for (int i = 0; i < 8; i++) {
        int m = ty * 8 + i;
        #pragma unroll
        for (int j = 0; j < 8; j++) {
            int n = tx * 8 + j;
            float h2 = __fadd_rn(acc[i][j], b2s[n]);
            H3[m * 129 + n] = softplus_x(h2);
        }
    }
    __syncthreads();

    // layer 3: cuBLAS gemv2T-8 order
    {
        int grp = tid >> 3;
        int l8  = tid & 7;
        #pragma unroll
        for (int rep = 0; rep < 4; rep++) {
            int m = rep * 32 + grp;
            const float* hrow = H3 + m * 129;
            float p = 0.0f;
            #pragma unroll
            for (int i = 0; i < 16; i++)
                p = __fmaf_rn(hrow[l8 + 8 * i], w3s[l8 + 8 * i], p);
            p = __fadd_rn(p, __shfl_down_sync(0xffffffffu, p, 4, 8));
            p = __fadd_rn(p, __shfl_down_sync(0xffffffffu, p, 2, 8));
            p = __fadd_rn(p, __shfl_down_sync(0xffffffffu, p, 1, 8));
            if (l8 == 0) {
                float corr = __fadd_rn(p, b3s[0]);
                float px = Ps[m * 4 + 0], py = Ps[m * 4 + 1], pz = Ps[m * 4 + 2];
                float s2 = __fadd_rn(__fadd_rn(__fmul_rn(px, px), __fmul_rn(py, py)), __fmul_rn(pz, pz));
                float nr = __fsqrt_rn(s2);
                float sv = __fadd_rn(__fsub_rn(nr, 1.0f), __fmul_rn(0.1f, corr));
                int oi = oix[m];
                if (oi >= 0) outp[oi] = sv;
            }
        }
    }
}

// ---------------- control kernels ----------------
__global__ void reset_kernel() {
    if (threadIdx.x < 64) g_cnt[threadIdx.x] = 0;
}

__global__ void init_kernel(const float* __restrict__ fb, const int* __restrict__ mi, int N) {
    int i = blockIdx.x * blockDim.x + threadIdx.x;
    if (i >= N) return;
    g_start[i] = fb[2 * i];
    g_end[i]   = fb[2 * i + 1];
    unsigned char m = mi[i] ? 1 : 0;
    g_uf_s[i] = m; g_uf_e[i] = m;
    g_next_s[i] = 0.f; g_next_e[i] = 0.f;
    g_workf[i] = 0; g_secf[i] = 0; g_convf[i] = 0;
    if (m) { int p = atomicAdd(&g_cnt[0], 1); g_la[p] = i; }
}

__global__ void update1_kernel(int apply_lt, int cs_idx, int ce_idx, int N) {
    int i = blockIdx.x * blockDim.x + threadIdx.x;
    if (i >= N) return;
    unsigned char us = g_uf_s[i], ue = g_uf_e[i];
    float s = g_start[i], e = g_end[i];
    if (apply_lt) { unsigned char lt = (s < e) ? 1 : 0; us &= lt; ue &= lt; }
    float cs = us ? g_next_s[i] : 0.f; if (cs <= THRS) cs = 0.f;
    float ce = ue ? g_next_e[i] : 0.f; if (ce <= THRS) ce = 0.f;
    us = (us && cs > THRS) ? 1 : 0;
    ue = (ue && ce > THRS) ? 1 : 0;
    if (us) s = __fadd_rn(s, cs);
    if (ue) e = __fsub_rn(e, ce);
    g_start[i] = s; g_end[i] = e;
    g_curr_s[i] = cs; g_curr_e[i] = ce;
    g_uf_s[i] = us; g_uf_e[i] = ue;
    // next = where(uf, sdf, 0): zero for dropped rays; eval rewrites listed rays
    if (!us) g_next_s[i] = 0.f;
    if (!ue) g_next_e[i] = 0.f;
    if (us) { int p = atomicAdd(&g_cnt[cs_idx], 1); g_la[p] = i; }
    if (ue) { int p = atomicAdd(&g_cnt[ce_idx], 1); g_lb[p] = i; }
}

__global__ void linestep_kernel(int cs_idx, int ce_idx, int N) {
    int i = blockIdx.x * blockDim.x + threadIdx.x;
    if (i >= N) return;
    if (g_uf_s[i] && g_next_s[i] < 0.f) {
        g_start[i] = __fsub_rn(g_start[i], __fmul_rn(0.5f, g_curr_s[i]));
        int p = atomicAdd(&g_cnt[cs_idx], 1); g_lc[p] = i;
    }
    if (g_uf_e[i] && g_next_e[i] < 0.f) {
        g_end[i] = __fadd_rn(g_end[i], __fmul_rn(0.5f, g_curr_e[i]));
        int p = atomicAdd(&g_cnt[ce_idx], 1); g_ld[p] = i;
    }
}

__global__ void work_kernel(int c_idx, int N) {
    int i = blockIdx.x * blockDim.x + threadIdx.x;
    if (i >= N) return;
    unsigned char us = g_uf_s[i];
    if (!(g_start[i] < g_end[i])) us = 0;
    unsigned char w = (us && (g_next_s[i] > THRS)) ? 1 : 0;
    g_workf[i] = w;
    if (w) { int p = atomicAdd(&g_cnt[c_idx], 1); g_lw[p] = i; }
}

// one warp per work-ray (via list): argmins over 64 dense samples + secant init
__global__ void reduce_kernel(const int* __restrict__ obj, int wc_idx, int sc_idx) {
    int warp = threadIdx.x >> 5, lane = threadIdx.x & 31;
    int li = blockIdx.x * 8 + warp;
    if (li >= g_cnt[wc_idx]) return;
    int ray = g_lw[li];
    float s0 = g_sdfval[ray * 64 + lane];
    float s1 = g_sdfval[ray * 64 + lane + 32];
    float sg0 = (s0 > 0.f ? 1.f : (s0 < 0.f ? -1.f : 0.f));
    float sg1 = (s1 > 0.f ? 1.f : (s1 < 0.f ? -1.f : 0.f));
    float t0 = sg0 * (float)(64 - lane);
    float t1 = sg1 * (float)(32 - lane);

    float bv; int bi;
    if (t1 < t0) { bv = t1; bi = lane + 32; } else { bv = t0; bi = lane; }
    float cv; int ci;
    if (s1 < s0) { cv = s1; ci = lane + 32; } else { cv = s0; ci = lane; }
    #pragma unroll
    for (int off = 16; off > 0; off >>= 1) {
        float ov = __shfl_down_sync(0xffffffffu, bv, off);
        int   oi = __shfl_down_sync(0xffffffffu, bi, off);
        if (ov < bv || (ov == bv && oi < bi)) { bv = ov; bi = oi; }
        float pv = __shfl_down_sync(0xffffffffu, cv, off);
        int   pi = __shfl_down_sync(0xffffffffu, ci, off);
        if (pv < cv || (pv == cv && pi < ci)) { cv = pv; ci = pi; }
    }
    if (lane == 0) {
        int idx = bi;
        bool net = (bv < 0.f);
        int out_idx = ci;
        bool ob = (obj[ray] != 0);
        bool p_out = !(ob && net);
        int sel = p_out ? out_idx : idx;
        float s = g_start[ray], e = g_end[ray];
        g_cand[ray]  = ptsint(s, e, lint(sel));
        g_convf[ray] = net ? 1 : 0;
        if (net && ob) {
            g_secf[ray] = 1;
            int il = (idx + 63) & 63;
            float zh = ptsint(s, e, lint(idx));
            float zl = ptsint(s, e, lint(il));
            float sh = g_sdfval[ray * 64 + idx];
            float sl = g_sdfval[ray * 64 + il];
            g_zlow[ray] = zl; g_zhigh[ray] = zh; g_slow[ray] = sl; g_shigh[ray] = sh;
            float num = __fmul_rn(-sl, __fsub_rn(zh, zl));
            float den = __fadd_rn(__fsub_rn(sh, sl), 1e-10f);
            g_zpred[ray] = __fadd_rn(__fdiv_rn(num, den), zl);
            int p = atomicAdd(&g_cnt[sc_idx], 1); g_ls[p] = ray;
        }
    }
}

__global__ void secant_kernel(int sc_idx) {
    int li = blockIdx.x * blockDim.x + threadIdx.x;
    if (li >= g_cnt[sc_idx]) return;
    int i = g_ls[li];
    float smv = g_smv[i];
    float zl = g_zlow[i], zh = g_zhigh[i], sl = g_slow[i], sh = g_shigh[i];
    float zp = g_zpred[i];
    if (smv > 0.f) { zl = zp; sl = smv; }
    if (smv < 0.f) { zh = zp; sh = smv; }
    float num = __fmul_rn(-sl, __fsub_rn(zh, zl));
    float den = __fadd_rn(__fsub_rn(sh, sl), 1e-10f);
    zp = __fadd_rn(__fdiv_rn(num, den), zl);
    g_zlow[i] = zl; g_zhigh[i] = zh; g_slow[i] = sl; g_shigh[i] = sh;
    g_zpred[i] = zp;
}

__global__ void assembly_kernel(const float* __restrict__ rayo, const float* __restrict__ rayd,
                                float* __restrict__ out, int N) {
    int i = blockIdx.x * blockDim.x + threadIdx.x;
    if (i >= N) return;
    float px = 0.f, py = 0.f, pz = 0.f, dist = 0.f;
    if (g_secf[i]) {
        float t = g_zpred[i];
        px = __fadd_rn(rayo[i*3+0], __fmul_rn(t, rayd[i*3+0]));
        py = __fadd_rn(rayo[i*3+1], __fmul_rn(t, rayd[i*3+1]));
        pz = __fadd_rn(rayo[i*3+2], __fmul_rn(t, rayd[i*3+2]));
        dist = t;
    } else if (g_workf[i]) {
        float t = g_cand[i];
        px = __fadd_rn(rayo[i*3+0], __fmul_rn(t, rayd[i*3+0]));
        py = __fadd_rn(rayo[i*3+1], __fmul_rn(t, rayd[i*3+1]));
        pz = __fadd_rn(rayo[i*3+2], __fmul_rn(t, rayd[i*3+2]));
        dist = t;
    }
    out[i*5+0] = px; out[i*5+1] = py; out[i*5+2] = pz;
    out[i*5+3] = dist;
    out[i*5+4] = g_convf[i] ? 1.0f : 0.0f;
}

// ---------------- host orchestration ----------------
extern "C" void kernel_launch(void* const* d_in, const int* in_sizes, int n_in,
                              void* d_out, int out_size)
{
    const float* rayo = (const float*)d_in[0];
    const float* rayd = (const float*)d_in[1];
    const float* fb   = (const float*)d_in[2];
    const float* W1   = (const float*)d_in[3];
    const float* b1   = (const float*)d_in[4];
    const float* W2   = (const float*)d_in[5];
    const float* b2   = (const float*)d_in[6];
    const float* W3   = (const float*)d_in[7];
    const float* b3   = (const float*)d_in[8];
    const int* obj    = (const int*)d_in[9];
    const int* mi     = (const int*)d_in[10];
    int N = in_sizes[0] / 3;
    float* out = (float*)d_out;

    cudaFuncSetAttribute(eval_kernel, cudaFuncAttributeMaxDynamicSharedMemorySize, EVAL_SMEM);

    float *p_start, *p_end, *p_ns, *p_ne, *p_zpred, *p_smv, *p_sdfval;
    int *p_la, *p_lb, *p_lc, *p_ld, *p_lw, *p_ls;
    cudaGetSymbolAddress((void**)&p_start,  g_start);
    cudaGetSymbolAddress((void**)&p_end,    g_end);
    cudaGetSymbolAddress((void**)&p_ns,     g_next_s);
    cudaGetSymbolAddress((void**)&p_ne,     g_next_e);
    cudaGetSymbolAddress((void**)&p_zpred,  g_zpred);
    cudaGetSymbolAddress((void**)&p_smv,    g_smv);
    cudaGetSymbolAddress((void**)&p_sdfval, g_sdfval);
    cudaGetSymbolAddress((void**)&p_la,     g_la);
    cudaGetSymbolAddress((void**)&p_lb,     g_lb);
    cudaGetSymbolAddress((void**)&p_lc,     g_lc);
    cudaGetSymbolAddress((void**)&p_ld,     g_ld);
    cudaGetSymbolAddress((void**)&p_lw,     g_lw);
    cudaGetSymbolAddress((void**)&p_ls,     g_ls);

    const int nb  = (N + 255) / 256;            // 64
    const int eg  = (N + TM - 1) / TM;          // 128
    const int egd = (N * NSTEPS + TM - 1) / TM; // 8192

    reset_kernel<<<1, 64>>>();
    init_kernel<<<nb, 256>>>(fb, mi, N);
    // initial next_s/next_e over mask list (both sides use list g_la, cnt 0)
    eval_kernel<<<2 * eg, 256, EVAL_SMEM>>>(0, 0, 0, eg, rayo, rayd, W1, b1, W2, b2, W3, b3,
                                            p_la, p_la, p_start, p_end, p_ns, p_ne);

    for (int it = 0; it < 10; it++) {
        int c1 = 1 + it * 4, c2 = 2 + it * 4, c3 = 3 + it * 4, c4 = 4 + it * 4;
        update1_kernel<<<nb, 256>>>(it > 0 ? 1 : 0, c1, c2, N);
        eval_kernel<<<2 * eg, 256, EVAL_SMEM>>>(0, c1, c2, eg, rayo, rayd, W1, b1, W2, b2, W3, b3,
                                                p_la, p_lb, p_start, p_end, p_ns, p_ne);
        linestep_kernel<<<nb, 256>>>(c3, c4, N);
        eval_kernel<<<2 * eg, 256, EVAL_SMEM>>>(0, c3, c4, eg, rayo, rayd, W1, b1, W2, b2, W3, b3,
                                                p_lc, p_ld, p_start, p_end, p_ns, p_ne);
    }

    work_kernel<<<nb, 256>>>(48, N);
    // dense 64-step march over work list only
    eval_kernel<<<egd, 256, EVAL_SMEM>>>(1, 48, 48, egd, rayo, rayd, W1, b1, W2, b2, W3, b3,
                                         p_lw, p_lw, p_start, p_start, p_sdfval, p_sdfval);
    reduce_kernel<<<(N + 7) / 8, 256>>>(obj, 48, 49);

    for (int it = 0; it < 8; it++) {
        eval_kernel<<<eg, 256, EVAL_SMEM>>>(0, 49, 49, eg, rayo, rayd, W1, b1, W2, b2, W3, b3,
                                            p_ls, p_ls, p_zpred, p_zpred, p_smv, p_smv);
        secant_kernel<<<nb, 256>>>(49);
    }

    assembly_kernel<<<nb, 256>>>(rayo, rayd, out, N);
    (void)n_in; (void)out_size; (void)b2;
}